// round 16
// baseline (speedup 1.0000x reference)
#include <cuda_runtime.h>
#include <math.h>

// x (B=32, C=256, H=64, W=64) fp32; s=mean_c(x); h=relu(s*w1+b1)[16];
// scale=sigmoid(w2@h+b2); out=x*scale
// Identity: z[c] = w2[c]@relu(s*w1+b1)+b2[c] is piecewise-linear in s:
//   z[c] = A[c,i]*s + B[c,i],  i = #{k : s > t_k},  t_k = -b1[k]/w1[k]
// R16: R13 (bench-best) with the FIRST tile's loads issued BEFORE the
// per-CTA table-build prologue, so the ~2-3us prologue executes under the
// first tile's DRAM latency instead of in front of it. Loop body ends with
// next-tile loads into the (now dead) v registers — same position across
// the back edge as R13, zero extra register cost.

#define B_    32
#define CH    256
#define HW4   1024          // 4096/4 float4 per (b,c) row
#define HID   16
#define P4    16            // float4 pixels per tile (64 px)
#define TPB   512
#define NGRP  32            // channel groups (t>>4)
#define CPT   8             // channels per thread -> v[8] = 32 regs
#define NTILE 2048          // 32 images * 64 tiles/image
#define GRID  296           // 2 persistent CTAs per SM * 148

__device__ __forceinline__ float sigmoid_tanh(float z) {
    float th;
    asm("tanh.approx.f32 %0, %1;" : "=f"(th) : "f"(0.5f * z));
    return fmaf(0.5f, th, 0.5f);
}

__global__ __launch_bounds__(TPB, 2)
void pse_fused_kernel(const float4* __restrict__ x,
                      const float*  __restrict__ w1,
                      const float*  __restrict__ b1,
                      const float*  __restrict__ w2,
                      const float*  __restrict__ b2,
                      float4* __restrict__ out)
{
    __shared__ float2 AB[CH * 17];        // 34,816 B piecewise-linear table
    __shared__ float4 red4[NGRP * P4];    //  8,192 B partial sums
    __shared__ float4 s4b[P4];
    __shared__ int4   i4b[P4];
    __shared__ float  us[HID];
    __shared__ float  reps[HID + 1];

    const int t = threadIdx.x;
    const int q = t & (P4 - 1);           // float4-pixel 0..15
    const int g = t >> 4;                 // channel group 0..31
    const float INF = __int_as_float(0x7f800000);

    // ---------- issue FIRST tile's loads before the prologue ----------
    int tile = blockIdx.x;
    float4 v[CPT];
    {
        const int img   = tile >> 6;          // 64 tiles per image
        const int base4 = (tile & 63) << 4;
        const float4* xb = x + (size_t)img * CH * HW4 + base4;
        #pragma unroll
        for (int j = 0; j < CPT; j++)
            v[j] = __ldcs(&xb[(g + j * NGRP) * HW4 + q]);   // in flight now
    }

    // ---------- per-CTA prologue (runs under first-tile DRAM latency) ----
    if (t < HID) {
        float w = w1[t], b = b1[t];
        float myth = (w != 0.0f) ? (-b / w) : INF;
        int rank = 0;
        #pragma unroll
        for (int k = 0; k < HID; k++) {
            float wk = w1[k], bk = b1[k];
            float tk = (wk != 0.0f) ? (-bk / wk) : INF;
            rank += (tk < myth) || (tk == myth && k < t);
        }
        us[rank] = myth;
    }
    __syncthreads();
    if (t < HID + 1) {
        float lo = (t == 0)   ? -INF : us[t - 1];
        float hi = (t == HID) ?  INF : us[t];
        bool flo = isfinite(lo), fhi = isfinite(hi);
        if (!flo && !fhi)      { lo = -1.0f; hi = 1.0f; }
        else if (!flo)         lo = hi - 2.0f;
        else if (!fhi)         hi = lo + 2.0f;
        reps[t] = 0.5f * (lo + hi);
    }
    __syncthreads();
    {   // 512 threads, 2 per channel: thread handles intervals i%2 == t&1
        const int c = t >> 1;
        const int half = t & 1;
        float w2r[HID];
        #pragma unroll
        for (int k = 0; k < HID; k++) w2r[k] = w2[c * HID + k];
        const float bc = b2[c];
        for (int i = half; i < 17; i += 2) {
            const float rep = reps[i];
            float a = 0.0f, bb = bc;
            #pragma unroll
            for (int k = 0; k < HID; k++) {
                float wk = w1[k], bk = b1[k];
                if (fmaf(rep, wk, bk) > 0.0f) {   // unit k active on interval i
                    a  = fmaf(w2r[k], wk, a);
                    bb = fmaf(w2r[k], bk, bb);
                }
            }
            AB[c * 17 + i] = make_float2(a, bb);
        }
    }
    __syncthreads();

    // ---------- persistent tile loop (v holds current tile on entry) ------
    for (; tile < NTILE; tile += GRID) {
        const int img   = tile >> 6;
        const int base4 = (tile & 63) << 4;
        float4* ob = out + (size_t)img * CH * HW4 + base4;

        // pass 1: per-thread pixel sums from preloaded registers
        float4 s = make_float4(0.f, 0.f, 0.f, 0.f);
        #pragma unroll
        for (int j = 0; j < CPT; j++) {
            s.x += v[j].x; s.y += v[j].y; s.z += v[j].z; s.w += v[j].w;
        }
        red4[g * P4 + q] = s;
        __syncthreads();

        // warp-0 two-half reduce: lane l -> pixel w=l&15, half h=l>>4 sums
        // 16 groups; shfl_xor(16) merges halves; lanes 0-15 classify.
        if (t < 32) {
            const int w = t & 15, h = t >> 4;
            float4 acc = red4[(h * 16) * P4 + w];
            #pragma unroll
            for (int g2 = 1; g2 < 16; g2++) {
                float4 r = red4[(h * 16 + g2) * P4 + w];
                acc.x += r.x; acc.y += r.y; acc.z += r.z; acc.w += r.w;
            }
            acc.x += __shfl_xor_sync(0xffffffffu, acc.x, 16);
            acc.y += __shfl_xor_sync(0xffffffffu, acc.y, 16);
            acc.z += __shfl_xor_sync(0xffffffffu, acc.z, 16);
            acc.w += __shfl_xor_sync(0xffffffffu, acc.w, 16);
            if (h == 0) {
                const float inv = 1.0f / (float)CH;
                float4 sv = make_float4(acc.x*inv, acc.y*inv, acc.z*inv, acc.w*inv);
                int4 iv = make_int4(0, 0, 0, 0);
                #pragma unroll
                for (int k = 0; k < HID; k++) {
                    const float tk = us[k];
                    iv.x += (sv.x > tk); iv.y += (sv.y > tk);
                    iv.z += (sv.z > tk); iv.w += (sv.w > tk);
                }
                s4b[w] = sv; i4b[w] = iv;
            }
        }
        __syncthreads();

        // pass 2: compute from registers + smem table; tanh-based sigmoid
        const float4 sv = s4b[q];
        const int4   iv = i4b[q];
        #pragma unroll
        for (int j = 0; j < CPT; j++) {
            const int c = g + j * NGRP;
            const float2* row = AB + c * 17;
            const float2 a0 = row[iv.x], a1 = row[iv.y],
                         a2 = row[iv.z], a3 = row[iv.w];
            const float z0 = fmaf(a0.x, sv.x, a0.y);
            const float z1 = fmaf(a1.x, sv.y, a1.y);
            const float z2 = fmaf(a2.x, sv.z, a2.y);
            const float z3 = fmaf(a3.x, sv.w, a3.y);
            float4 o;
            o.x = v[j].x * sigmoid_tanh(z0);
            o.y = v[j].y * sigmoid_tanh(z1);
            o.z = v[j].z * sigmoid_tanh(z2);
            o.w = v[j].w * sigmoid_tanh(z3);
            __stcs(&ob[c * HW4 + q], o);                    // never re-read
        }

        // load NEXT tile into the now-dead v registers (same position
        // across the back edge as R13's top-of-body loads)
        const int next = tile + GRID;
        if (next < NTILE) {
            const int nimg   = next >> 6;
            const int nbase4 = (next & 63) << 4;
            const float4* xn = x + (size_t)nimg * CH * HW4 + nbase4;
            #pragma unroll
            for (int j = 0; j < CPT; j++)
                v[j] = __ldcs(&xn[(g + j * NGRP) * HW4 + q]);
        }
        // next iteration's red4/s4b writes are fenced by its __syncthreads()
    }
}

extern "C" void kernel_launch(void* const* d_in, const int* in_sizes, int n_in,
                              void* d_out, int out_size)
{
    pse_fused_kernel<<<GRID, TPB>>>((const float4*)d_in[0],
                                    (const float*)d_in[1],
                                    (const float*)d_in[2],
                                    (const float*)d_in[3],
                                    (const float*)d_in[4],
                                    (float4*)d_out);
}

// round 17
// speedup vs baseline: 1.4279x; 1.4279x over previous
#include <cuda_runtime.h>
#include <math.h>

// x (B=32, C=256, H=64, W=64) fp32; s=mean_c(x); h=relu(s*w1+b1)[16];
// scale=sigmoid(w2@h+b2); out=x*scale
// Identity: z[c] = w2[c]@relu(s*w1+b1)+b2[c] is piecewise-linear in s:
//   z[c] = A[c,i]*s + B[c,i],  i = #{k : s > t_k},  t_k = -b1[k]/w1[k]
// FINAL (R13): persistent kernel, 512 thr, 64-px tiles, x held in registers
// via a front-batched 8x LDG.128 __ldcs burst (MLP=8 — do not scatter these),
// smem piecewise-linear table, warp-0 two-half reduce, HW tanh sigmoid,
// __stcs streaming stores. 2 CTAs/SM, grid 296.

#define B_    32
#define CH    256
#define HW4   1024          // 4096/4 float4 per (b,c) row
#define HID   16
#define P4    16            // float4 pixels per tile (64 px)
#define TPB   512
#define NGRP  32            // channel groups (t>>4)
#define CPT   8             // channels per thread -> v[8] = 32 regs
#define NTILE 2048          // 32 images * 64 tiles/image
#define GRID  296           // 2 persistent CTAs per SM * 148

__device__ __forceinline__ float sigmoid_tanh(float z) {
    float th;
    asm("tanh.approx.f32 %0, %1;" : "=f"(th) : "f"(0.5f * z));
    return fmaf(0.5f, th, 0.5f);
}

__global__ __launch_bounds__(TPB, 2)
void pse_fused_kernel(const float4* __restrict__ x,
                      const float*  __restrict__ w1,
                      const float*  __restrict__ b1,
                      const float*  __restrict__ w2,
                      const float*  __restrict__ b2,
                      float4* __restrict__ out)
{
    __shared__ float2 AB[CH * 17];        // 34,816 B piecewise-linear table
    __shared__ float4 red4[NGRP * P4];    //  8,192 B partial sums
    __shared__ float4 s4b[P4];
    __shared__ int4   i4b[P4];
    __shared__ float  us[HID];
    __shared__ float  reps[HID + 1];

    const int t = threadIdx.x;
    const int q = t & (P4 - 1);           // float4-pixel 0..15
    const int g = t >> 4;                 // channel group 0..31
    const float INF = __int_as_float(0x7f800000);

    // ---------- per-CTA prologue: build piecewise-linear table ----------
    if (t < HID) {
        float w = w1[t], b = b1[t];
        float myth = (w != 0.0f) ? (-b / w) : INF;
        int rank = 0;
        #pragma unroll
        for (int k = 0; k < HID; k++) {
            float wk = w1[k], bk = b1[k];
            float tk = (wk != 0.0f) ? (-bk / wk) : INF;
            rank += (tk < myth) || (tk == myth && k < t);
        }
        us[rank] = myth;
    }
    __syncthreads();
    if (t < HID + 1) {
        float lo = (t == 0)   ? -INF : us[t - 1];
        float hi = (t == HID) ?  INF : us[t];
        bool flo = isfinite(lo), fhi = isfinite(hi);
        if (!flo && !fhi)      { lo = -1.0f; hi = 1.0f; }
        else if (!flo)         lo = hi - 2.0f;
        else if (!fhi)         hi = lo + 2.0f;
        reps[t] = 0.5f * (lo + hi);
    }
    __syncthreads();
    {   // 512 threads, 2 per channel: thread handles intervals i%2 == t&1
        const int c = t >> 1;
        const int half = t & 1;
        float w2r[HID];
        #pragma unroll
        for (int k = 0; k < HID; k++) w2r[k] = w2[c * HID + k];
        const float bc = b2[c];
        for (int i = half; i < 17; i += 2) {
            const float rep = reps[i];
            float a = 0.0f, bb = bc;
            #pragma unroll
            for (int k = 0; k < HID; k++) {
                float wk = w1[k], bk = b1[k];
                if (fmaf(rep, wk, bk) > 0.0f) {   // unit k active on interval i
                    a  = fmaf(w2r[k], wk, a);
                    bb = fmaf(w2r[k], bk, bb);
                }
            }
            AB[c * 17 + i] = make_float2(a, bb);
        }
    }
    __syncthreads();

    // ---------- persistent tile loop ----------
    for (int tile = blockIdx.x; tile < NTILE; tile += GRID) {
        const int img   = tile >> 6;          // 64 tiles per image
        const int base4 = (tile & 63) << 4;
        const float4* xb = x   + (size_t)img * CH * HW4 + base4;
        float4*       ob = out + (size_t)img * CH * HW4 + base4;

        // pass 1: 8 independent LDG.128 into registers (front-batched burst)
        float4 v[CPT];
        #pragma unroll
        for (int j = 0; j < CPT; j++)
            v[j] = __ldcs(&xb[(g + j * NGRP) * HW4 + q]);   // read-once data

        float4 s = make_float4(0.f, 0.f, 0.f, 0.f);
        #pragma unroll
        for (int j = 0; j < CPT; j++) {
            s.x += v[j].x; s.y += v[j].y; s.z += v[j].z; s.w += v[j].w;
        }
        red4[g * P4 + q] = s;
        __syncthreads();

        // warp-0 two-half reduce: lane l -> pixel w=l&15, half h=l>>4 sums
        // 16 groups; shfl_xor(16) merges halves; lanes 0-15 classify.
        if (t < 32) {
            const int w = t & 15, h = t >> 4;
            float4 acc = red4[(h * 16) * P4 + w];
            #pragma unroll
            for (int g2 = 1; g2 < 16; g2++) {
                float4 r = red4[(h * 16 + g2) * P4 + w];
                acc.x += r.x; acc.y += r.y; acc.z += r.z; acc.w += r.w;
            }
            acc.x += __shfl_xor_sync(0xffffffffu, acc.x, 16);
            acc.y += __shfl_xor_sync(0xffffffffu, acc.y, 16);
            acc.z += __shfl_xor_sync(0xffffffffu, acc.z, 16);
            acc.w += __shfl_xor_sync(0xffffffffu, acc.w, 16);
            if (h == 0) {
                const float inv = 1.0f / (float)CH;
                float4 sv = make_float4(acc.x*inv, acc.y*inv, acc.z*inv, acc.w*inv);
                int4 iv = make_int4(0, 0, 0, 0);
                #pragma unroll
                for (int k = 0; k < HID; k++) {
                    const float tk = us[k];
                    iv.x += (sv.x > tk); iv.y += (sv.y > tk);
                    iv.z += (sv.z > tk); iv.w += (sv.w > tk);
                }
                s4b[w] = sv; i4b[w] = iv;
            }
        }
        __syncthreads();

        // pass 2: compute from registers + smem table; tanh-based sigmoid
        const float4 sv = s4b[q];
        const int4   iv = i4b[q];
        #pragma unroll
        for (int j = 0; j < CPT; j++) {
            const int c = g + j * NGRP;
            const float2* row = AB + c * 17;
            const float2 a0 = row[iv.x], a1 = row[iv.y],
                         a2 = row[iv.z], a3 = row[iv.w];
            const float z0 = fmaf(a0.x, sv.x, a0.y);
            const float z1 = fmaf(a1.x, sv.y, a1.y);
            const float z2 = fmaf(a2.x, sv.z, a2.y);
            const float z3 = fmaf(a3.x, sv.w, a3.y);
            float4 o;
            o.x = v[j].x * sigmoid_tanh(z0);
            o.y = v[j].y * sigmoid_tanh(z1);
            o.z = v[j].z * sigmoid_tanh(z2);
            o.w = v[j].w * sigmoid_tanh(z3);
            __stcs(&ob[c * HW4 + q], o);                    // never re-read
        }
        // next tile's red4/s4b writes are fenced by its own __syncthreads()
    }
}

extern "C" void kernel_launch(void* const* d_in, const int* in_sizes, int n_in,
                              void* d_out, int out_size)
{
    pse_fused_kernel<<<GRID, TPB>>>((const float4*)d_in[0],
                                    (const float*)d_in[1],
                                    (const float*)d_in[2],
                                    (const float*)d_in[3],
                                    (const float*)d_in[4],
                                    (float4*)d_out);
}